// round 14
// baseline (speedup 1.0000x reference)
#include <cuda_runtime.h>
#include <cuda_fp16.h>
#include <cstdint>

#define LATENT 64
#define OUT    128
#define H      32
#define BM     64    // rows per CTA
#define PITCH  144   // bytes per smem A row (72 fp16) — conflict-free ldmatrix

// smem layout (dynamic)
#define SM_SP    0
#define SM_SN    512
#define SM_B3    1024
#define SM_AHI   1536
#define SM_TOTAL (SM_AHI + BM * PITCH)   // 10752 (4 CTAs/SM)

// Scratch (no device allocation allowed)
__device__ float g_sp[OUT];
__device__ float g_sn[OUT];
__device__ int   g_slow = 0;
// B mma fragments, fp16, permuted-d lane layout (see precompute):
// u32 index = (((wn*4+g)*4+s)*32 + flane)*2 + reg
__device__ __align__(16) uint32_t g_bf[4 * 4 * 4 * 32 * 2];

// ---------------------------------------------------------------------------
// PTX helpers (family-portable only: ldmatrix + mma.sync)
// ---------------------------------------------------------------------------
__device__ __forceinline__ uint32_t smem_u32(const void* p) {
    uint32_t a;
    asm("{ .reg .u64 t; cvta.to.shared.u64 t, %1; cvt.u32.u64 %0, t; }"
        : "=r"(a) : "l"(p));
    return a;
}
#define LDSM_X4(r0, r1, r2, r3, addr)                                          \
    asm volatile("ldmatrix.sync.aligned.m8n8.x4.shared.b16 {%0,%1,%2,%3}, [%4];" \
                 : "=r"(r0), "=r"(r1), "=r"(r2), "=r"(r3) : "r"(addr))
#define MMA_F16(c, a, b)                                                       \
    asm volatile("mma.sync.aligned.m16n8k16.row.col.f32.f16.f16.f32 "          \
                 "{%0,%1,%2,%3},{%4,%5,%6,%7},{%8,%9},{%0,%1,%2,%3};"          \
                 : "+f"((c)[0]), "+f"((c)[1]), "+f"((c)[2]), "+f"((c)[3])      \
                 : "r"((a)[0]), "r"((a)[1]), "r"((a)[2]), "r"((a)[3]),         \
                   "r"((b)[0]), "r"((b)[1]))

__device__ __forceinline__ uint32_t pack_h2(float a, float b) {
    __half2 h = __floats2half2_rn(a, b);
    return *(uint32_t*)&h;
}

// ---------------------------------------------------------------------------
// Precompute (one block per feature d, 32 lanes):
//  - collapsed slopes sp/sn (valid when b1==b2==0; sets g_slow otherwise)
//  - fp16 B fragments of |Wp| with PERMUTED feature->column mapping so the
//    epilogue's per-thread columns are contiguous:
//      tile g   = (d>>1)&3
//      B n-pos  = 2*((d>>3)&3) + (d&1)
//    => thread L owns logical cols d = wn*32 + (L%4)*8 + {0..7}.
// ---------------------------------------------------------------------------
__global__ void precompute_kernel(const float* __restrict__ Wp,
                                  const float* __restrict__ W1,
                                  const float* __restrict__ b1,
                                  const float* __restrict__ W2,
                                  const float* __restrict__ b2,
                                  const float* __restrict__ W3)
{
    const int d    = blockIdx.x;
    const int lane = threadIdx.x;

    // Issue all loads up front
    float  w1v = W1[d * H + lane];
    float  b1v = b1[d * H + lane];
    float  b2v = b2[d * H + lane];
    float  w3  = W3[d * H + lane];
    const float4* w2 = (const float4*)(W2 + ((long)d * H + lane) * H);
    float4 w2v[8];
#pragma unroll
    for (int q = 0; q < H / 4; ++q) w2v[q] = w2[q];

    // B fragments: mma m16n8k16 B operand, lane group 4*nb..4*nb+3 holds n=nb.
    // reg0: k = kq*2 + {0,1}; reg1: k = 8 + kq*2 + {0,1}  (kq = lane&3 of group)
    if (lane < 16) {
        const int s  = lane >> 2;
        const int kq = lane & 3;
        const int k0 = s * 16 + kq * 2;
        float f0 = fabsf(Wp[d * LATENT + k0]);
        float f1 = fabsf(Wp[d * LATENT + k0 + 1]);
        float f2 = fabsf(Wp[d * LATENT + k0 + 8]);
        float f3 = fabsf(Wp[d * LATENT + k0 + 9]);
        const int wn    = d >> 5;
        const int g     = (d >> 1) & 3;                    // permuted tile
        const int nb    = 2 * ((d >> 3) & 3) + (d & 1);    // permuted n-pos
        const int flane = nb * 4 + kq;
        const int idx   = ((((wn * 4 + g) * 4 + s) * 32) + flane) * 2;
        g_bf[idx]     = pack_h2(f0, f1);
        g_bf[idx + 1] = pack_h2(f2, f3);
    }

    int nz = (b1v != 0.f) | (b2v != 0.f);

    float up = 0.f, un = 0.f;
#pragma unroll
    for (int q = 0; q < H / 4; ++q) {
        float wv[4] = {w2v[q].x, w2v[q].y, w2v[q].z, w2v[q].w};
#pragma unroll
        for (int j = 0; j < 4; ++j) {
            float w1h = __shfl_sync(0xffffffffu, w1v, q * 4 + j);
            up = fmaf(wv[j], fmaxf(w1h, 0.f), up);
            un = fmaf(wv[j], fmaxf(-w1h, 0.f), un);
        }
    }
    float tp = w3 * fmaxf(up, 0.f);
    float tn = w3 * fmaxf(un, 0.f);
#pragma unroll
    for (int off = 16; off > 0; off >>= 1) {
        tp += __shfl_down_sync(0xffffffffu, tp, off);
        tn += __shfl_down_sync(0xffffffffu, tn, off);
    }
    unsigned any_nz = __ballot_sync(0xffffffffu, nz);
    if (lane == 0) {
        g_sp[d] = tp;
        g_sn[d] = tn;
        if (any_nz) atomicOr(&g_slow, 1);
    }
}

// ---------------------------------------------------------------------------
// Main: single-term fp16 mma.sync GEMM (BM=64 x 128, K=64) + fused epilogue.
// A = rn(z) fp16 via smem+ldmatrix; B = fp16 fragments streamed from gmem.
// Permuted feature mapping -> epilogue writes 2x STG.128 per row per thread.
// 8 warps, warp tile 32(m) x 32(n), 4 CTAs/SM.
// ---------------------------------------------------------------------------
__global__ __launch_bounds__(256, 4) void main_kernel(
    const float* __restrict__ z,  const float* __restrict__ Wp,
    const float* __restrict__ W1, const float* __restrict__ b1,
    const float* __restrict__ W2, const float* __restrict__ b2,
    const float* __restrict__ W3, const float* __restrict__ b3,
    float* __restrict__ out, long total)
{
    if (g_slow) {   // exact fallback path (never taken when b1==b2==0)
        for (long idx = (long)blockIdx.x * blockDim.x + threadIdx.x; idx < total;
             idx += (long)gridDim.x * blockDim.x) {
            int n = (int)(idx >> 7);
            int d = (int)(idx & (OUT - 1));
            float y = 0.f;
#pragma unroll
            for (int k = 0; k < LATENT; ++k)
                y = fmaf(z[(long)n * LATENT + k], fabsf(Wp[d * LATENT + k]), y);
            float h1[H];
#pragma unroll
            for (int h = 0; h < H; ++h)
                h1[h] = fmaxf(fmaf(y, W1[d * H + h], b1[d * H + h]), 0.f);
            float x = b3[d];
#pragma unroll 4
            for (int k = 0; k < H; ++k) {
                float t = b2[d * H + k];
                const float* w2 = W2 + ((long)d * H + k) * H;
#pragma unroll
                for (int h = 0; h < H; ++h) t = fmaf(w2[h], h1[h], t);
                x = fmaf(W3[d * H + k], fmaxf(t, 0.f), x);
            }
            out[idx] = fabsf(x);
        }
        return;
    }

    extern __shared__ char smem[];
    const uint32_t sb = smem_u32(smem);
    const int tid  = threadIdx.x;
    const int wid  = tid >> 5;
    const int lane = tid & 31;
    const int wm   = wid >> 2;   // 0..1 -> rows wm*32
    const int wn   = wid & 3;    // 0..3 -> cols wn*32
    const int brow = blockIdx.x * BM;

    // z tile loads first (deepest latency): 64 rows x 64 f32.
    const int zrow = tid >> 2;
    const int zseg = tid & 3;
    const float4* zr = (const float4*)(z + (size_t)(brow + zrow) * LATENT + zseg * 16);
    float4 v[4];
#pragma unroll
    for (int j = 0; j < 4; ++j) v[j] = __ldcs(zr + j);

    // Prefetch B fragments for s=0 (gmem, L2/L1-hot).
    // Strides (u32): wn:1024, g:256, s:64, lane:2.
    const uint32_t* bfbase = g_bf + (size_t)wn * 1024 + lane * 2;
    uint32_t bcur[4][2], bnxt[4][2];
#pragma unroll
    for (int g = 0; g < 4; ++g) {
        uint2 t = *(const uint2*)(bfbase + g * 256);
        bcur[g][0] = t.x; bcur[g][1] = t.y;
    }

    // Stage epilogue constants (sn sign-folded)
    if (tid < OUT) {
        ((float*)(smem + SM_SP))[tid] = g_sp[tid];
        ((float*)(smem + SM_SN))[tid] = -g_sn[tid];
        ((float*)(smem + SM_B3))[tid] = b3[tid];
    }

    // fp16 convert of z into smem (single term: A = rn(z))
    {
        uint4 uh0, uh1;
        uh0.x = pack_h2(v[0].x, v[0].y); uh0.y = pack_h2(v[0].z, v[0].w);
        uh0.z = pack_h2(v[1].x, v[1].y); uh0.w = pack_h2(v[1].z, v[1].w);
        uh1.x = pack_h2(v[2].x, v[2].y); uh1.y = pack_h2(v[2].z, v[2].w);
        uh1.z = pack_h2(v[3].x, v[3].y); uh1.w = pack_h2(v[3].z, v[3].w);
        int off = zrow * PITCH + zseg * 32;   // 16 floats -> 32 bytes fp16
        *(uint4*)(smem + SM_AHI + off)      = uh0;
        *(uint4*)(smem + SM_AHI + off + 16) = uh1;
    }
    __syncthreads();

    // ldmatrix lane base address (A)
    const uint32_t aoff = sb + SM_AHI + (uint32_t)((wm * 32 + (lane & 15)) * PITCH +
                                                   (lane >> 4) * 16);

    float acc[2][4][4];
#pragma unroll
    for (int f = 0; f < 2; ++f)
#pragma unroll
        for (int g = 0; g < 4; ++g)
#pragma unroll
            for (int e = 0; e < 4; ++e) acc[f][g][e] = 0.f;

    // K=64 in 4 k16 steps; B frags double-buffered from gmem.
#pragma unroll
    for (int s = 0; s < 4; ++s) {
        if (s < 3) {
#pragma unroll
            for (int g = 0; g < 4; ++g) {
                uint2 t = *(const uint2*)(bfbase + (s + 1) * 64 + g * 256);
                bnxt[g][0] = t.x; bnxt[g][1] = t.y;
            }
        }
        uint32_t ah[2][4];
#pragma unroll
        for (int f = 0; f < 2; ++f)
            LDSM_X4(ah[f][0], ah[f][1], ah[f][2], ah[f][3],
                    aoff + f * 16 * PITCH + s * 32);
#pragma unroll
        for (int f = 0; f < 2; ++f)
#pragma unroll
            for (int g = 0; g < 4; ++g)
                MMA_F16(acc[f][g], ah[f], bcur[g]);
        if (s < 3) {
#pragma unroll
            for (int g = 0; g < 4; ++g) {
                bcur[g][0] = bnxt[g][0]; bcur[g][1] = bnxt[g][1];
            }
        }
    }

    // Fused epilogue: thread owns 8 contiguous cols dbase..dbase+7.
    // acc[f][g][half*2+j] -> col dbase + 2g + j, row = wm*32+f*16+qrow+half*8.
    {
        const int p     = lane & 3;
        const int qrow  = lane >> 2;
        const int dbase = wn * 32 + p * 8;
        const float* sps = (const float*)(smem + SM_SP) + dbase;
        const float* sns = (const float*)(smem + SM_SN) + dbase;   // already -sn
        const float* b3s = (const float*)(smem + SM_B3) + dbase;
        float spv[8], snv[8], bbv[8];
#pragma unroll
        for (int c = 0; c < 8; ++c) {
            spv[c] = sps[c]; snv[c] = sns[c]; bbv[c] = b3s[c];
        }
#pragma unroll
        for (int f = 0; f < 2; ++f) {
#pragma unroll
            for (int half = 0; half < 2; ++half) {
                const int r = brow + wm * 32 + f * 16 + qrow + half * 8;
                float o[8];
#pragma unroll
                for (int g = 0; g < 4; ++g) {
#pragma unroll
                    for (int j = 0; j < 2; ++j) {
                        const int c = g * 2 + j;
                        float y = acc[f][g][half * 2 + j];
                        o[c] = fabsf(fmaf(y, (y > 0.f ? spv[c] : snv[c]), bbv[c]));
                    }
                }
                float* op = out + (size_t)r * OUT + dbase;
                __stcs((float4*)op,       make_float4(o[0], o[1], o[2], o[3]));
                __stcs((float4*)(op + 4), make_float4(o[4], o[5], o[6], o[7]));
            }
        }
    }
}

// ---------------------------------------------------------------------------
extern "C" void kernel_launch(void* const* d_in, const int* in_sizes, int n_in,
                              void* d_out, int out_size)
{
    const float* z  = (const float*)d_in[0];
    const float* Wp = (const float*)d_in[1];
    const float* W1 = (const float*)d_in[2];
    const float* b1 = (const float*)d_in[3];
    const float* W2 = (const float*)d_in[4];
    const float* b2 = (const float*)d_in[5];
    const float* W3 = (const float*)d_in[6];
    const float* b3 = (const float*)d_in[7];
    float* out = (float*)d_out;

    int nrows = in_sizes[0] / LATENT;   // 65536

    cudaFuncSetAttribute(main_kernel,
                         cudaFuncAttributeMaxDynamicSharedMemorySize, SM_TOTAL);

    precompute_kernel<<<OUT, 32>>>(Wp, W1, b1, W2, b2, W3);
    main_kernel<<<nrows / BM, 256, SM_TOTAL>>>(z, Wp, W1, b1, W2, b2, W3, b3,
                                               out, (long)nrows * OUT);
}

// round 15
// speedup vs baseline: 1.0256x; 1.0256x over previous
#include <cuda_runtime.h>
#include <cuda_fp16.h>
#include <cstdint>

#define LATENT 64
#define OUT    128
#define H      32
#define BM     64    // rows per tile
#define PITCH  144   // bytes per smem A row (72 fp16) — conflict-free ldmatrix
#define GRID   444   // 3 persistent CTAs per SM (148 SMs), grid-stride tiles

// smem layout (dynamic)
#define SM_SP    0
#define SM_SN    512
#define SM_B3    1024
#define SM_ZS    1536                      // f32 z staging, 64 rows x 272B pitch
#define SM_A0    (SM_ZS + 64 * 272)        // 18944, fp16 tile buf0 (9216)
#define SM_A1    (SM_A0 + BM * PITCH)      // 28160, fp16 tile buf1
#define SM_TOTAL (SM_A1 + BM * PITCH)      // 37376 (3 CTAs/SM)

// Scratch (no device allocation allowed)
__device__ float g_sp[OUT];
__device__ float g_sn[OUT];
__device__ int   g_slow = 0;
// B mma fragments, fp16, exact mma B-operand lane layout:
// u32 index = (((wn*4+g)*4+s)*32 + lane)*2 + reg
__device__ __align__(16) uint32_t g_bf[4 * 4 * 4 * 32 * 2];

// ---------------------------------------------------------------------------
// PTX helpers (family-portable only: ldmatrix + mma.sync + cp.async)
// ---------------------------------------------------------------------------
__device__ __forceinline__ uint32_t smem_u32(const void* p) {
    uint32_t a;
    asm("{ .reg .u64 t; cvta.to.shared.u64 t, %1; cvt.u32.u64 %0, t; }"
        : "=r"(a) : "l"(p));
    return a;
}
#define LDSM_X4(r0, r1, r2, r3, addr)                                          \
    asm volatile("ldmatrix.sync.aligned.m8n8.x4.shared.b16 {%0,%1,%2,%3}, [%4];" \
                 : "=r"(r0), "=r"(r1), "=r"(r2), "=r"(r3) : "r"(addr))
#define MMA_F16(c, a, b)                                                       \
    asm volatile("mma.sync.aligned.m16n8k16.row.col.f32.f16.f16.f32 "          \
                 "{%0,%1,%2,%3},{%4,%5,%6,%7},{%8,%9},{%0,%1,%2,%3};"          \
                 : "+f"((c)[0]), "+f"((c)[1]), "+f"((c)[2]), "+f"((c)[3])      \
                 : "r"((a)[0]), "r"((a)[1]), "r"((a)[2]), "r"((a)[3]),         \
                   "r"((b)[0]), "r"((b)[1]))
#define CP_ASYNC16(smem_addr, gptr)                                            \
    asm volatile("cp.async.cg.shared.global [%0], [%1], 16;"                   \
                 :: "r"(smem_addr), "l"(gptr))

__device__ __forceinline__ uint32_t pack_h2(float a, float b) {
    __half2 h = __floats2half2_rn(a, b);
    return *(uint32_t*)&h;
}

// ---------------------------------------------------------------------------
// Precompute (one block per feature d, 32 lanes):
//  - collapsed slopes sp/sn (valid when b1==b2==0; sets g_slow otherwise)
//  - fp16 B fragments of |Wp| in exact mma B lane layout (lanes 0-15)
// ---------------------------------------------------------------------------
__global__ void precompute_kernel(const float* __restrict__ Wp,
                                  const float* __restrict__ W1,
                                  const float* __restrict__ b1,
                                  const float* __restrict__ W2,
                                  const float* __restrict__ b2,
                                  const float* __restrict__ W3)
{
    const int d    = blockIdx.x;
    const int lane = threadIdx.x;

    // Issue all loads up front
    float  w1v = W1[d * H + lane];
    float  b1v = b1[d * H + lane];
    float  b2v = b2[d * H + lane];
    float  w3  = W3[d * H + lane];
    const float4* w2 = (const float4*)(W2 + ((long)d * H + lane) * H);
    float4 w2v[8];
#pragma unroll
    for (int q = 0; q < H / 4; ++q) w2v[q] = w2[q];

    // B fragments: mma m16n8k16 B operand, lane L holds b[k][n], n = L/4,
    // reg0: k = (L%4)*2 + {0,1}; reg1: k = 8 + (L%4)*2 + {0,1}
    if (lane < 16) {
        const int s  = lane >> 2;
        const int kq = lane & 3;
        const int k0 = s * 16 + kq * 2;
        float f0 = fabsf(Wp[d * LATENT + k0]);
        float f1 = fabsf(Wp[d * LATENT + k0 + 1]);
        float f2 = fabsf(Wp[d * LATENT + k0 + 8]);
        float f3 = fabsf(Wp[d * LATENT + k0 + 9]);
        const int wn    = d >> 5;
        const int g     = (d >> 3) & 3;
        const int flane = (d & 7) * 4 + kq;
        const int idx   = ((((wn * 4 + g) * 4 + s) * 32) + flane) * 2;
        g_bf[idx]     = pack_h2(f0, f1);
        g_bf[idx + 1] = pack_h2(f2, f3);
    }

    int nz = (b1v != 0.f) | (b2v != 0.f);

    float up = 0.f, un = 0.f;
#pragma unroll
    for (int q = 0; q < H / 4; ++q) {
        float wv[4] = {w2v[q].x, w2v[q].y, w2v[q].z, w2v[q].w};
#pragma unroll
        for (int j = 0; j < 4; ++j) {
            float w1h = __shfl_sync(0xffffffffu, w1v, q * 4 + j);
            up = fmaf(wv[j], fmaxf(w1h, 0.f), up);
            un = fmaf(wv[j], fmaxf(-w1h, 0.f), un);
        }
    }
    float tp = w3 * fmaxf(up, 0.f);
    float tn = w3 * fmaxf(un, 0.f);
#pragma unroll
    for (int off = 16; off > 0; off >>= 1) {
        tp += __shfl_down_sync(0xffffffffu, tp, off);
        tn += __shfl_down_sync(0xffffffffu, tn, off);
    }
    unsigned any_nz = __ballot_sync(0xffffffffu, nz);
    if (lane == 0) {
        g_sp[d] = tp;
        g_sn[d] = tn;
        if (any_nz) atomicOr(&g_slow, 1);
    }
}

// ---------------------------------------------------------------------------
// Main: persistent CTAs (grid-stride tiles), single-term fp16 mma.sync GEMM
// (64 x 128 x 64 per tile) + fused epilogue.
//  - B fragments in registers for the whole CTA (no gmem in steady state)
//  - z prefetched one tile ahead via cp.async into f32 smem staging
//  - A fp16 double-buffered; one __syncthreads per tile
// ---------------------------------------------------------------------------
__global__ __launch_bounds__(256, 3) void main_kernel(
    const float* __restrict__ z,  const float* __restrict__ Wp,
    const float* __restrict__ W1, const float* __restrict__ b1,
    const float* __restrict__ W2, const float* __restrict__ b2,
    const float* __restrict__ W3, const float* __restrict__ b3,
    float* __restrict__ out, long total, int ntiles)
{
    if (g_slow) {   // exact fallback path (never taken when b1==b2==0)
        for (long idx = (long)blockIdx.x * blockDim.x + threadIdx.x; idx < total;
             idx += (long)gridDim.x * blockDim.x) {
            int n = (int)(idx >> 7);
            int d = (int)(idx & (OUT - 1));
            float y = 0.f;
#pragma unroll
            for (int k = 0; k < LATENT; ++k)
                y = fmaf(z[(long)n * LATENT + k], fabsf(Wp[d * LATENT + k]), y);
            float h1[H];
#pragma unroll
            for (int h = 0; h < H; ++h)
                h1[h] = fmaxf(fmaf(y, W1[d * H + h], b1[d * H + h]), 0.f);
            float x = b3[d];
#pragma unroll 4
            for (int k = 0; k < H; ++k) {
                float t = b2[d * H + k];
                const float* w2 = W2 + ((long)d * H + k) * H;
#pragma unroll
                for (int h = 0; h < H; ++h) t = fmaf(w2[h], h1[h], t);
                x = fmaf(W3[d * H + k], fmaxf(t, 0.f), x);
            }
            out[idx] = fabsf(x);
        }
        return;
    }

    int t = blockIdx.x;
    if (t >= ntiles) return;   // CTA-uniform

    extern __shared__ char smem[];
    const uint32_t sb = smem_u32(smem);
    const int tid  = threadIdx.x;
    const int wid  = tid >> 5;
    const int lane = tid & 31;
    const int wm   = wid >> 2;   // 0..1 -> rows wm*32
    const int wn   = wid & 3;    // 0..3 -> cols wn*32
    const int zrow = tid >> 2;   // 0..63
    const int zseg = tid & 3;    // 0..3 (16 floats / 64 bytes each)

    // Stage epilogue constants (sn sign-folded)
    if (tid < OUT) {
        ((float*)(smem + SM_SP))[tid] = g_sp[tid];
        ((float*)(smem + SM_SN))[tid] = -g_sn[tid];
        ((float*)(smem + SM_B3))[tid] = b3[tid];
    }

    // B fragments: load once, keep in registers for all tiles.
    uint32_t bf[4][4][2];        // [s][g][reg]
#pragma unroll
    for (int g = 0; g < 4; ++g)
#pragma unroll
        for (int s = 0; s < 4; ++s) {
            uint2 t2 = *(const uint2*)(g_bf + ((wn * 4 + g) * 4 + s) * 64 + lane * 2);
            bf[s][g][0] = t2.x; bf[s][g][1] = t2.y;
        }

    // ZSTAGE: 272B pitch (17x16B) to spread smem bank groups.
    const int      zsoff  = SM_ZS + zrow * 272 + zseg * 64;
    const uint32_t zsaddr = sb + zsoff;
    const uint32_t alane  = (uint32_t)((wm * 32 + (lane & 15)) * PITCH +
                                       (lane >> 4) * 16);
    const int      aconv  = zrow * PITCH + zseg * 32;  // convert STS offset

    // Prologue: prefetch z(tile t)
    {
        const char* src = (const char*)(z + ((size_t)t * BM + zrow) * LATENT + zseg * 16);
#pragma unroll
        for (int j = 0; j < 4; ++j) CP_ASYNC16(zsaddr + j * 16, src + j * 16);
        asm volatile("cp.async.commit_group;" ::: "memory");
    }

    int cur = 0;
    while (true) {
        // z(t) arrived (this thread reads exactly the bytes it copied)
        asm volatile("cp.async.wait_group 0;" ::: "memory");
        float4 f0 = *(const float4*)(smem + zsoff);
        float4 f1 = *(const float4*)(smem + zsoff + 16);
        float4 f2 = *(const float4*)(smem + zsoff + 32);
        float4 f3 = *(const float4*)(smem + zsoff + 48);

        // Prefetch z(t+GRID) — ZSTAGE reads above already in flight/regs
        const int  next     = t + GRID;
        const bool has_next = next < ntiles;
        if (has_next) {
            const char* src = (const char*)(z + ((size_t)next * BM + zrow) * LATENT + zseg * 16);
#pragma unroll
            for (int j = 0; j < 4; ++j) CP_ASYNC16(zsaddr + j * 16, src + j * 16);
            asm volatile("cp.async.commit_group;" ::: "memory");
        }

        // Convert f32 -> fp16 into A[cur]
        {
            uint4 uh0, uh1;
            uh0.x = pack_h2(f0.x, f0.y); uh0.y = pack_h2(f0.z, f0.w);
            uh0.z = pack_h2(f1.x, f1.y); uh0.w = pack_h2(f1.z, f1.w);
            uh1.x = pack_h2(f2.x, f2.y); uh1.y = pack_h2(f2.z, f2.w);
            uh1.z = pack_h2(f3.x, f3.y); uh1.w = pack_h2(f3.z, f3.w);
            int ab = (cur ? SM_A1 : SM_A0) + aconv;
            *(uint4*)(smem + ab)      = uh0;
            *(uint4*)(smem + ab + 16) = uh1;
        }
        __syncthreads();   // A[cur] complete for all warps

        // Mainloop: LDSM + MMA only (B in registers)
        const uint32_t aoff = sb + (cur ? SM_A1 : SM_A0) + alane;
        float acc[2][4][4];
#pragma unroll
        for (int f = 0; f < 2; ++f)
#pragma unroll
            for (int g = 0; g < 4; ++g)
#pragma unroll
                for (int e = 0; e < 4; ++e) acc[f][g][e] = 0.f;

#pragma unroll
        for (int s = 0; s < 4; ++s) {
            uint32_t ah[2][4];
#pragma unroll
            for (int f = 0; f < 2; ++f)
                LDSM_X4(ah[f][0], ah[f][1], ah[f][2], ah[f][3],
                        aoff + f * 16 * PITCH + s * 32);
#pragma unroll
            for (int f = 0; f < 2; ++f)
#pragma unroll
                for (int g = 0; g < 4; ++g)
                    MMA_F16(acc[f][g], ah[f], bf[s][g]);
        }

        // Fused epilogue (sign-folded slopes; streaming stores)
        {
            const int brow = t * BM;
            const int qrow = lane >> 2;
            const int qcol = 2 * (lane & 3);
            const float* sps = (const float*)(smem + SM_SP);
            const float* sns = (const float*)(smem + SM_SN);   // already -sn
            const float* b3s = (const float*)(smem + SM_B3);
#pragma unroll
            for (int g = 0; g < 4; ++g) {
                const int c0 = wn * 32 + g * 8 + qcol;
                float sp0 = sps[c0], sp1 = sps[c0 + 1];
                float sn0 = sns[c0], sn1 = sns[c0 + 1];
                float t0  = b3s[c0], t1  = b3s[c0 + 1];
#pragma unroll
                for (int f = 0; f < 2; ++f) {
                    const int r0 = brow + wm * 32 + f * 16 + qrow;
                    float y0 = acc[f][g][0], y1 = acc[f][g][1];
                    float y2 = acc[f][g][2], y3 = acc[f][g][3];
                    float o0 = fabsf(fmaf(y0, (y0 > 0.f ? sp0 : sn0), t0));
                    float o1 = fabsf(fmaf(y1, (y1 > 0.f ? sp1 : sn1), t1));
                    float o2 = fabsf(fmaf(y2, (y2 > 0.f ? sp0 : sn0), t0));
                    float o3 = fabsf(fmaf(y3, (y3 > 0.f ? sp1 : sn1), t1));
                    __stcs((float2*)(out + (size_t)r0 * OUT + c0),       make_float2(o0, o1));
                    __stcs((float2*)(out + (size_t)(r0 + 8) * OUT + c0), make_float2(o2, o3));
                }
            }
        }

        if (!has_next) break;
        t = next;
        cur ^= 1;
    }
}

// ---------------------------------------------------------------------------
extern "C" void kernel_launch(void* const* d_in, const int* in_sizes, int n_in,
                              void* d_out, int out_size)
{
    const float* z  = (const float*)d_in[0];
    const float* Wp = (const float*)d_in[1];
    const float* W1 = (const float*)d_in[2];
    const float* b1 = (const float*)d_in[3];
    const float* W2 = (const float*)d_in[4];
    const float* b2 = (const float*)d_in[5];
    const float* W3 = (const float*)d_in[6];
    const float* b3 = (const float*)d_in[7];
    float* out = (float*)d_out;

    int nrows  = in_sizes[0] / LATENT;   // 65536
    int ntiles = nrows / BM;             // 1024

    cudaFuncSetAttribute(main_kernel,
                         cudaFuncAttributeMaxDynamicSharedMemorySize, SM_TOTAL);

    precompute_kernel<<<OUT, 32>>>(Wp, W1, b1, W2, b2, W3);
    main_kernel<<<GRID, 256, SM_TOTAL>>>(z, Wp, W1, b1, W2, b2, W3, b3,
                                         out, (long)nrows * OUT, ntiles);
}

// round 16
// speedup vs baseline: 1.1385x; 1.1101x over previous
#include <cuda_runtime.h>
#include <cuda_fp16.h>
#include <cstdint>

#define LATENT 64
#define OUT    128
#define H      32
#define BM     64    // rows per CTA
#define PITCH  144   // bytes per smem A row (72 fp16) — conflict-free ldmatrix

// smem layout (dynamic): dual constant copies (one per half-CTA) + A tile
#define SM_SP0   0
#define SM_SN0   512
#define SM_B30   1024
#define SM_SP1   1536
#define SM_SN1   2048
#define SM_B31   2560
#define SM_AHI   3072
#define SM_TOTAL (SM_AHI + BM * PITCH)   // 12288

// Scratch (no device allocation allowed)
__device__ float g_sp[OUT];
__device__ float g_sn[OUT];
__device__ int   g_slow = 0;
// B mma fragments, fp16, exact mma B-operand lane layout:
// u32 index = (((wn*4+g)*4+s)*32 + lane)*2 + reg
__device__ __align__(16) uint32_t g_bf[4 * 4 * 4 * 32 * 2];

// ---------------------------------------------------------------------------
// PTX helpers (family-portable only: ldmatrix + mma.sync)
// ---------------------------------------------------------------------------
__device__ __forceinline__ uint32_t smem_u32(const void* p) {
    uint32_t a;
    asm("{ .reg .u64 t; cvta.to.shared.u64 t, %1; cvt.u32.u64 %0, t; }"
        : "=r"(a) : "l"(p));
    return a;
}
#define LDSM_X4(r0, r1, r2, r3, addr)                                          \
    asm volatile("ldmatrix.sync.aligned.m8n8.x4.shared.b16 {%0,%1,%2,%3}, [%4];" \
                 : "=r"(r0), "=r"(r1), "=r"(r2), "=r"(r3) : "r"(addr))
#define MMA_F16(c, a, b)                                                       \
    asm volatile("mma.sync.aligned.m16n8k16.row.col.f32.f16.f16.f32 "          \
                 "{%0,%1,%2,%3},{%4,%5,%6,%7},{%8,%9},{%0,%1,%2,%3};"          \
                 : "+f"((c)[0]), "+f"((c)[1]), "+f"((c)[2]), "+f"((c)[3])      \
                 : "r"((a)[0]), "r"((a)[1]), "r"((a)[2]), "r"((a)[3]),         \
                   "r"((b)[0]), "r"((b)[1]))

__device__ __forceinline__ uint32_t pack_h2(float a, float b) {
    __half2 h = __floats2half2_rn(a, b);
    return *(uint32_t*)&h;
}

// ---------------------------------------------------------------------------
// Precompute (one block per feature d, 32 lanes):
//  - collapsed slopes sp/sn (valid when b1==b2==0; sets g_slow otherwise)
//  - fp16 B fragments of |Wp| in exact mma B lane layout (lanes 0-15)
// ---------------------------------------------------------------------------
__global__ void precompute_kernel(const float* __restrict__ Wp,
                                  const float* __restrict__ W1,
                                  const float* __restrict__ b1,
                                  const float* __restrict__ W2,
                                  const float* __restrict__ b2,
                                  const float* __restrict__ W3)
{
    const int d    = blockIdx.x;
    const int lane = threadIdx.x;

    // Issue all loads up front
    float  w1v = W1[d * H + lane];
    float  b1v = b1[d * H + lane];
    float  b2v = b2[d * H + lane];
    float  w3  = W3[d * H + lane];
    const float4* w2 = (const float4*)(W2 + ((long)d * H + lane) * H);
    float4 w2v[8];
#pragma unroll
    for (int q = 0; q < H / 4; ++q) w2v[q] = w2[q];

    // B fragments: mma m16n8k16 B operand, lane L holds b[k][n], n = L/4,
    // reg0: k = (L%4)*2 + {0,1}; reg1: k = 8 + (L%4)*2 + {0,1}
    if (lane < 16) {
        const int s  = lane >> 2;
        const int kq = lane & 3;
        const int k0 = s * 16 + kq * 2;
        float f0 = fabsf(Wp[d * LATENT + k0]);
        float f1 = fabsf(Wp[d * LATENT + k0 + 1]);
        float f2 = fabsf(Wp[d * LATENT + k0 + 8]);
        float f3 = fabsf(Wp[d * LATENT + k0 + 9]);
        const int wn    = d >> 5;
        const int g     = (d >> 3) & 3;
        const int flane = (d & 7) * 4 + kq;
        const int idx   = ((((wn * 4 + g) * 4 + s) * 32) + flane) * 2;
        g_bf[idx]     = pack_h2(f0, f1);
        g_bf[idx + 1] = pack_h2(f2, f3);
    }

    int nz = (b1v != 0.f) | (b2v != 0.f);

    float up = 0.f, un = 0.f;
#pragma unroll
    for (int q = 0; q < H / 4; ++q) {
        float wv[4] = {w2v[q].x, w2v[q].y, w2v[q].z, w2v[q].w};
#pragma unroll
        for (int j = 0; j < 4; ++j) {
            float w1h = __shfl_sync(0xffffffffu, w1v, q * 4 + j);
            up = fmaf(wv[j], fmaxf(w1h, 0.f), up);
            un = fmaf(wv[j], fmaxf(-w1h, 0.f), un);
        }
    }
    float tp = w3 * fmaxf(up, 0.f);
    float tn = w3 * fmaxf(un, 0.f);
#pragma unroll
    for (int off = 16; off > 0; off >>= 1) {
        tp += __shfl_down_sync(0xffffffffu, tp, off);
        tn += __shfl_down_sync(0xffffffffu, tn, off);
    }
    unsigned any_nz = __ballot_sync(0xffffffffu, nz);
    if (lane == 0) {
        g_sp[d] = tp;
        g_sn[d] = tn;
        if (any_nz) atomicOr(&g_slow, 1);
    }
}

// ---------------------------------------------------------------------------
// Main: single-term fp16 mma.sync GEMM (BM=64 x 128, K=64) + fused epilogue.
// A = rn(z) fp16 via smem+ldmatrix; B fragments fully register-resident.
// Half-CTA decoupling: warps 0-3 consume rows written by threads 0-127,
// warps 4-7 rows from threads 128-255 -> named barriers, dual const copies.
// 8 warps, warp tile 32(m) x 32(n), 3 CTAs/SM.
// ---------------------------------------------------------------------------
__global__ __launch_bounds__(256, 3) void main_kernel(
    const float* __restrict__ z,  const float* __restrict__ Wp,
    const float* __restrict__ W1, const float* __restrict__ b1,
    const float* __restrict__ W2, const float* __restrict__ b2,
    const float* __restrict__ W3, const float* __restrict__ b3,
    float* __restrict__ out, long total)
{
    if (g_slow) {   // exact fallback path (never taken when b1==b2==0)
        for (long idx = (long)blockIdx.x * blockDim.x + threadIdx.x; idx < total;
             idx += (long)gridDim.x * blockDim.x) {
            int n = (int)(idx >> 7);
            int d = (int)(idx & (OUT - 1));
            float y = 0.f;
#pragma unroll
            for (int k = 0; k < LATENT; ++k)
                y = fmaf(z[(long)n * LATENT + k], fabsf(Wp[d * LATENT + k]), y);
            float h1[H];
#pragma unroll
            for (int h = 0; h < H; ++h)
                h1[h] = fmaxf(fmaf(y, W1[d * H + h], b1[d * H + h]), 0.f);
            float x = b3[d];
#pragma unroll 4
            for (int k = 0; k < H; ++k) {
                float t = b2[d * H + k];
                const float* w2 = W2 + ((long)d * H + k) * H;
#pragma unroll
                for (int h = 0; h < H; ++h) t = fmaf(w2[h], h1[h], t);
                x = fmaf(W3[d * H + k], fmaxf(t, 0.f), x);
            }
            out[idx] = fabsf(x);
        }
        return;
    }

    extern __shared__ char smem[];
    const uint32_t sb = smem_u32(smem);
    const int tid  = threadIdx.x;
    const int wid  = tid >> 5;
    const int lane = tid & 31;
    const int wm   = wid >> 2;   // 0..1 -> rows wm*32; also half-CTA id
    const int wn   = wid & 3;    // 0..3 -> cols wn*32
    const int brow = blockIdx.x * BM;

    // z tile loads first (deepest latency): 64 rows x 64 f32.
    const int zrow = tid >> 2;
    const int zseg = tid & 3;
    const float4* zr = (const float4*)(z + (size_t)(brow + zrow) * LATENT + zseg * 16);
    float4 v[4];
#pragma unroll
    for (int j = 0; j < 4; ++j) v[j] = __ldcs(zr + j);

    // B fragments: all 16 loads up front, register-resident (L2/L1-hot).
    // Strides (u32): wn:1024, g:256, s:64, lane:2.
    const uint32_t* bfbase = g_bf + (size_t)wn * 1024 + lane * 2;
    uint32_t bf[4][4][2];   // [s][g][reg]
#pragma unroll
    for (int g = 0; g < 4; ++g)
#pragma unroll
        for (int s = 0; s < 4; ++s) {
            uint2 t = *(const uint2*)(bfbase + g * 256 + s * 64);
            bf[s][g][0] = t.x; bf[s][g][1] = t.y;
        }

    // Stage epilogue constants: one copy per half-CTA (sn sign-folded).
    {
        const int  hid = tid >> 7;            // 0: threads 0-127, 1: 128-255
        const int  c   = tid & 127;
        const int  base = hid ? SM_SP1 : SM_SP0;
        ((float*)(smem + base))[c]        = g_sp[c];
        ((float*)(smem + base + 512))[c]  = -g_sn[c];
        ((float*)(smem + base + 1024))[c] = b3[c];
    }

    // fp16 convert of z into smem (single term: A = rn(z))
    {
        uint4 uh0, uh1;
        uh0.x = pack_h2(v[0].x, v[0].y); uh0.y = pack_h2(v[0].z, v[0].w);
        uh0.z = pack_h2(v[1].x, v[1].y); uh0.w = pack_h2(v[1].z, v[1].w);
        uh1.x = pack_h2(v[2].x, v[2].y); uh1.y = pack_h2(v[2].z, v[2].w);
        uh1.z = pack_h2(v[3].x, v[3].y); uh1.w = pack_h2(v[3].z, v[3].w);
        int off = zrow * PITCH + zseg * 32;   // 16 floats -> 32 bytes fp16
        *(uint4*)(smem + SM_AHI + off)      = uh0;
        *(uint4*)(smem + SM_AHI + off + 16) = uh1;
    }
    // Half-CTA barrier: warps 0-3 sync with threads 0-127 (rows 0-31),
    // warps 4-7 with threads 128-255 (rows 32-63).
    asm volatile("bar.sync %0, 128;" :: "r"(1 + wm) : "memory");

    // ldmatrix lane base address (A)
    const uint32_t aoff = sb + SM_AHI + (uint32_t)((wm * 32 + (lane & 15)) * PITCH +
                                                   (lane >> 4) * 16);

    float acc[2][4][4];
#pragma unroll
    for (int f = 0; f < 2; ++f)
#pragma unroll
        for (int g = 0; g < 4; ++g)
#pragma unroll
            for (int e = 0; e < 4; ++e) acc[f][g][e] = 0.f;

    // K=64 in 4 k16 steps; B in registers, loop = LDSM + MMA only.
#pragma unroll
    for (int s = 0; s < 4; ++s) {
        uint32_t ah[2][4];
#pragma unroll
        for (int f = 0; f < 2; ++f)
            LDSM_X4(ah[f][0], ah[f][1], ah[f][2], ah[f][3],
                    aoff + f * 16 * PITCH + s * 32);
#pragma unroll
        for (int f = 0; f < 2; ++f)
#pragma unroll
            for (int g = 0; g < 4; ++g)
                MMA_F16(acc[f][g], ah[f], bf[s][g]);
    }

    // Fused epilogue (sign-folded slopes; plain write-back stores).
    {
        const int qrow = lane >> 2;
        const int qcol = 2 * (lane & 3);
        const int cbase = wm ? SM_SP1 : SM_SP0;
        const float* sps = (const float*)(smem + cbase);
        const float* sns = (const float*)(smem + cbase + 512);    // already -sn
        const float* b3s = (const float*)(smem + cbase + 1024);
#pragma unroll
        for (int g = 0; g < 4; ++g) {
            const int c0 = wn * 32 + g * 8 + qcol;
            float sp0 = sps[c0], sp1 = sps[c0 + 1];
            float sn0 = sns[c0], sn1 = sns[c0 + 1];
            float t0  = b3s[c0], t1  = b3s[c0 + 1];
#pragma unroll
            for (int f = 0; f < 2; ++f) {
                const int r0 = brow + wm * 32 + f * 16 + qrow;
                float y0 = acc[f][g][0], y1 = acc[f][g][1];
                float y2 = acc[f][g][2], y3 = acc[f][g][3];
                float o0 = fabsf(fmaf(y0, (y0 > 0.f ? sp0 : sn0), t0));
                float o1 = fabsf(fmaf(y1, (y1 > 0.f ? sp1 : sn1), t1));
                float o2 = fabsf(fmaf(y2, (y2 > 0.f ? sp0 : sn0), t0));
                float o3 = fabsf(fmaf(y3, (y3 > 0.f ? sp1 : sn1), t1));
                *(float2*)(out + (size_t)r0 * OUT + c0)       = make_float2(o0, o1);
                *(float2*)(out + (size_t)(r0 + 8) * OUT + c0) = make_float2(o2, o3);
            }
        }
    }
}

// ---------------------------------------------------------------------------
extern "C" void kernel_launch(void* const* d_in, const int* in_sizes, int n_in,
                              void* d_out, int out_size)
{
    const float* z  = (const float*)d_in[0];
    const float* Wp = (const float*)d_in[1];
    const float* W1 = (const float*)d_in[2];
    const float* b1 = (const float*)d_in[3];
    const float* W2 = (const float*)d_in[4];
    const float* b2 = (const float*)d_in[5];
    const float* W3 = (const float*)d_in[6];
    const float* b3 = (const float*)d_in[7];
    float* out = (float*)d_out;

    int nrows = in_sizes[0] / LATENT;   // 65536

    cudaFuncSetAttribute(main_kernel,
                         cudaFuncAttributeMaxDynamicSharedMemorySize, SM_TOTAL);

    precompute_kernel<<<OUT, 32>>>(Wp, W1, b1, W2, b2, W3);
    main_kernel<<<nrows / BM, 256, SM_TOTAL>>>(z, Wp, W1, b1, W2, b2, W3, b3,
                                               out, (long)nrows * OUT);
}